// round 15
// baseline (speedup 1.0000x reference)
#include <cuda_runtime.h>
#include <cuda_fp16.h>
#include <cstdint>

// Problem constants (B,H,S,D) = (8,8,2048,64)
#define PB 8
#define PH 8
#define PS 2048
#define PD 64
#define INV_T 0.125f
#define LOG2E 1.44269504f
#define EXP_OFF 5.77078016f   // 4 * log2(e): P = exp(sim - 4) = exp2(sim*log2e - OFF)

constexpr int TILE_M = 128;  // i-rows per CTA (8 warps x 16 rows)
constexpr int TILE_N = 32;   // j-cols per iteration
constexpr int QS  = 72;      // halves stride: sQ/sK rows (conflict-free frag reads)
constexpr int VSS = 40;      // halves stride: sVt rows (conflict-free frag reads)
constexpr int PMS = 40;      // words stride: pos/mask rows (conflict-free float2 reads)

// ---- smem byte layout (identical to R11) ----
constexpr int KBUF_B   = TILE_N * QS * 2;         // 4608
constexpr int VBUF_B   = PD * VSS * 2;            // 5120
constexpr int REGA_B   = 2 * KBUF_B + 2 * VBUF_B; // 19456 (>= 18432 sQ prologue)
constexpr int PMPLANE_B = TILE_M * PMS * 4;       // 20480
constexpr int PM_B      = REGA_B;
constexpr int SMEM_BYTES = PM_B + 4 * PMPLANE_B;  // 101376 -> 2 CTAs/SM

// ---- persistent fp16 copies of K (row-major) and V (transposed, d-major) ----
__device__ __half g_kh[(size_t)PB * PH * PS * PD];
__device__ __half g_vt[(size_t)PB * PH * PD * PS];

__device__ __forceinline__ uint32_t h2pack(float a, float b) {
    __half2 h = __floats2half2_rn(a, b);
    return *reinterpret_cast<uint32_t*>(&h);
}

__device__ __forceinline__ float ex2f(float x) {
    float r;
    asm("ex2.approx.ftz.f32 %0, %1;" : "=f"(r) : "f"(x));
    return r;
}

__device__ __forceinline__ void mma_f16(float c[4], const uint32_t a[4],
                                        uint32_t b0, uint32_t b1) {
    asm volatile(
        "mma.sync.aligned.m16n8k16.row.col.f32.f16.f16.f32 "
        "{%0,%1,%2,%3}, {%4,%5,%6,%7}, {%8,%9}, {%0,%1,%2,%3};"
        : "+f"(c[0]), "+f"(c[1]), "+f"(c[2]), "+f"(c[3])
        : "r"(a[0]), "r"(a[1]), "r"(a[2]), "r"(a[3]),
          "r"(b0), "r"(b1));
}

__device__ __forceinline__ uint32_t smem_u32(const void* p) {
    uint32_t a;
    asm("{ .reg .u64 t; cvta.to.shared.u64 t, %1; cvt.u32.u64 %0, t; }" : "=r"(a) : "l"(p));
    return a;
}

// ================= prep: K -> fp16, V -> fp16 transposed =================
__global__ __launch_bounds__(256)
void prep_kv_kernel(const float* __restrict__ k, const float* __restrict__ v)
{
    __shared__ __half sv[32][72];
    const int bh  = blockIdx.y;
    const int j0  = blockIdx.x * 32;
    const int tid = threadIdx.x;

    const float* kb = k + (size_t)bh * PS * PD;
    const float* vb = v + (size_t)bh * PS * PD;
    __half* khb = g_kh + (size_t)bh * PS * PD;
    __half* vtb = g_vt + (size_t)bh * PD * PS;

    #pragma unroll
    for (int p = 0; p < 2; ++p) {
        int idx = p * 256 + tid;
        int r = idx >> 4, c4 = idx & 15;
        float4 kf = *(const float4*)(kb + (size_t)(j0 + r) * PD + c4 * 4);
        *(uint2*)(khb + (size_t)(j0 + r) * PD + c4 * 4) =
            make_uint2(h2pack(kf.x, kf.y), h2pack(kf.z, kf.w));
        float4 vf = *(const float4*)(vb + (size_t)(j0 + r) * PD + c4 * 4);
        sv[r][c4 * 4 + 0] = __float2half_rn(vf.x);
        sv[r][c4 * 4 + 1] = __float2half_rn(vf.y);
        sv[r][c4 * 4 + 2] = __float2half_rn(vf.z);
        sv[r][c4 * 4 + 3] = __float2half_rn(vf.w);
    }
    __syncthreads();

    int d = tid >> 2, ch = tid & 3;
    __half hb[8];
    #pragma unroll
    for (int jj = 0; jj < 8; ++jj) hb[jj] = sv[ch * 8 + jj][d];
    *(uint4*)(vtb + (size_t)d * PS + j0 + ch * 8) = *(uint4*)hb;
}

// ================= main attention kernel: 8 warps x m16 =================
__global__ __launch_bounds__(256, 2)
void attn_f16_w8_kernel(const float* __restrict__ q,
                        const float* __restrict__ pos,
                        const float* __restrict__ mask,
                        float* __restrict__ out)
{
    extern __shared__ uint32_t smw[];
    char* smb = (char*)smw;
    const uint32_t sb = smem_u32(smw);

    const int bx   = blockIdx.x;                // itile*8 + b
    const int h    = blockIdx.y;
    const int b    = bx & 7;
    const int i0   = (bx >> 3) * TILE_M;
    const int tid  = threadIdx.x;
    const int warp = tid >> 5;                   // 0..7
    const int lane = tid & 31;
    const int tg   = lane >> 2;
    const int tc   = lane & 3;

    const size_t bh = (size_t)(b * PH + h);
    const float*  qb   = q    + bh * (size_t)PS * PD;
    const __half* khb  = g_kh + bh * (size_t)PS * PD;
    const __half* vtb  = g_vt + bh * (size_t)PD * PS;
    const float*  posb = pos  + (size_t)h * PS * PS;
    float*        ob   = out  + bh * (size_t)PS * PD;

    // ---- stage K/Vt/pos/mask for tile at j0t into buffer buf (all cp.async) ----
    auto issue_tile = [&](int j0t, int buf) {
        if (j0t < PS) {
            const __half* kg = khb + (size_t)j0t * PD;
            const __half* vg = vtb + j0t;
            uint32_t kbase = sb + buf * KBUF_B;
            uint32_t vbase = sb + 2 * KBUF_B + buf * VBUF_B;
            {   // K: 32 rows x 8 chunks of 16B  (256 cp.async, 1/thread)
                int r = tid >> 3, ch = tid & 7;
                asm volatile("cp.async.cg.shared.global [%0], [%1], 16;"
                             :: "r"(kbase + r * (QS * 2) + ch * 16),
                                "l"(kg + (size_t)r * PD + ch * 8));
            }
            {   // Vt: 64 rows x 4 chunks of 16B (256 cp.async, 1/thread)
                int r = tid >> 2, ch = tid & 3;
                asm volatile("cp.async.cg.shared.global [%0], [%1], 16;"
                             :: "r"(vbase + r * (VSS * 2) + ch * 16),
                                "l"(vg + (size_t)r * PS + ch * 8));
            }
            uint32_t pbase = sb + PM_B + buf * 2 * PMPLANE_B;
            uint32_t mbase = pbase + PMPLANE_B;
            #pragma unroll
            for (int p = 0; p < 4; ++p) {
                int idx = p * 256 + tid;          // 0..1023
                int r = idx >> 3, ch = idx & 7;   // row 0..127, 16B chunk 0..7
                asm volatile("cp.async.cg.shared.global [%0], [%1], 16;"
                             :: "r"(pbase + r * (PMS * 4) + ch * 16),
                                "l"(posb + (size_t)(i0 + r) * PS + j0t + ch * 4));
                asm volatile("cp.async.cg.shared.global [%0], [%1], 16;"
                             :: "r"(mbase + r * (PMS * 4) + ch * 16),
                                "l"(mask + (size_t)(i0 + r) * PS + j0t + ch * 4));
            }
        }
        asm volatile("cp.async.commit_group;" ::: "memory");
    };

    // ---- prologue: stage Q tile (128x64 fp16), cache fragments ----
    __half* sQh = (__half*)smb;
    #pragma unroll
    for (int p = 0; p < 8; ++p) {
        int idx = p * 256 + tid;
        int r = idx >> 4, c4 = idx & 15;
        float4 f = *(const float4*)(qb + (size_t)(i0 + r) * PD + c4 * 4);
        *(uint2*)&sQh[r * QS + c4 * 4] = make_uint2(h2pack(f.x, f.y), h2pack(f.z, f.w));
    }
    __syncthreads();

    uint32_t qa[4][4];
    {
        const int rbase = warp * 16;
        #pragma unroll
        for (int ks = 0; ks < 4; ++ks) {
            int c0 = ks * 16 + tc * 2;
            qa[ks][0] = *(const uint32_t*)&sQh[(rbase + tg) * QS + c0];
            qa[ks][1] = *(const uint32_t*)&sQh[(rbase + tg + 8) * QS + c0];
            qa[ks][2] = *(const uint32_t*)&sQh[(rbase + tg) * QS + c0 + 8];
            qa[ks][3] = *(const uint32_t*)&sQh[(rbase + tg + 8) * QS + c0 + 8];
        }
    }
    __syncthreads();           // region A becomes K/Vt buffers
    issue_tile(0, 0);          // G0

    float l_i[2] = {0.f, 0.f};
    float o[8][4];
    #pragma unroll
    for (int n = 0; n < 8; ++n) { o[n][0] = o[n][1] = o[n][2] = o[n][3] = 0.f; }

    for (int it = 0; it < PS / TILE_N; ++it) {
        const int buf = it & 1;
        __syncthreads();                             // WAR: prev readers of buf^1 done
        issue_tile((it + 1) * TILE_N, buf ^ 1);      // G(it+1)
        asm volatile("cp.async.wait_group 1;" ::: "memory");  // G(it) complete
        __syncthreads();                             // visibility

        const __half* sKh  = (const __half*)(smb + buf * KBUF_B);
        const __half* sVth = (const __half*)(smb + 2 * KBUF_B + buf * VBUF_B);
        const float* sPosB = (const float*)(smb + PM_B + buf * 2 * PMPLANE_B);
        const float* sMskB = (const float*)(smb + PM_B + buf * 2 * PMPLANE_B + PMPLANE_B);

        // ---- S = Q K^T  (m16 x n32, ks-outer, 4 independent chains) ----
        float c[4][4];
        #pragma unroll
        for (int n = 0; n < 4; ++n) { c[n][0] = c[n][1] = c[n][2] = c[n][3] = 0.f; }
        #pragma unroll
        for (int ks = 0; ks < 4; ++ks) {
            #pragma unroll
            for (int n = 0; n < 4; ++n) {
                const __half* kr = &sKh[(n * 8 + tg) * QS + ks * 16 + tc * 2];
                mma_f16(c[n], qa[ks], *(const uint32_t*)kr, *(const uint32_t*)(kr + 8));
            }
        }

        // ---- P = exp(mask*(s*invT + pos) - 4); accumulate l per-thread ----
        {
            const int r0 = warp * 16 + tg;
            const int r1 = r0 + 8;
            float rs0 = 0.f, rs1 = 0.f;
            #pragma unroll
            for (int n = 0; n < 4; ++n) {
                int col = n * 8 + tc * 2;
                float2 p0  = *(const float2*)&sPosB[r0 * PMS + col];
                float2 p1  = *(const float2*)&sPosB[r1 * PMS + col];
                float2 mk0 = *(const float2*)&sMskB[r0 * PMS + col];
                float2 mk1 = *(const float2*)&sMskB[r1 * PMS + col];
                c[n][0] = ex2f(mk0.x * (c[n][0] * INV_T + p0.x) * LOG2E - EXP_OFF);
                c[n][1] = ex2f(mk0.y * (c[n][1] * INV_T + p0.y) * LOG2E - EXP_OFF);
                c[n][2] = ex2f(mk1.x * (c[n][2] * INV_T + p1.x) * LOG2E - EXP_OFF);
                c[n][3] = ex2f(mk1.y * (c[n][3] * INV_T + p1.y) * LOG2E - EXP_OFF);
                rs0 += c[n][0] + c[n][1];
                rs1 += c[n][2] + c[n][3];
            }
            l_i[0] += rs0;
            l_i[1] += rs1;
        }

        // ---- O += P V : P A-frags from registers, Vt B-frags scalar LDS ----
        #pragma unroll
        for (int ks = 0; ks < 2; ++ks) {
            uint32_t pa[4];
            pa[0] = h2pack(c[2 * ks][0],     c[2 * ks][1]);
            pa[1] = h2pack(c[2 * ks][2],     c[2 * ks][3]);
            pa[2] = h2pack(c[2 * ks + 1][0], c[2 * ks + 1][1]);
            pa[3] = h2pack(c[2 * ks + 1][2], c[2 * ks + 1][3]);
            #pragma unroll
            for (int nd = 0; nd < 8; ++nd) {
                const __half* vr = &sVth[(nd * 8 + tg) * VSS + ks * 16 + tc * 2];
                mma_f16(o[nd], pa, *(const uint32_t*)vr, *(const uint32_t*)(vr + 8));
            }
        }
    }

    // ---- epilogue: reduce l across group threads, normalize, write ----
    {
        float l0 = l_i[0], l1 = l_i[1];
        l0 += __shfl_xor_sync(0xffffffffu, l0, 1);
        l0 += __shfl_xor_sync(0xffffffffu, l0, 2);
        l1 += __shfl_xor_sync(0xffffffffu, l1, 1);
        l1 += __shfl_xor_sync(0xffffffffu, l1, 2);
        const float inv0 = 1.f / l0;
        const float inv1 = 1.f / l1;
        const int r0 = i0 + warp * 16 + tg;
        const int r1 = r0 + 8;
        #pragma unroll
        for (int nd = 0; nd < 8; ++nd) {
            float2 w0 = make_float2(o[nd][0] * inv0, o[nd][1] * inv0);
            float2 w1 = make_float2(o[nd][2] * inv1, o[nd][3] * inv1);
            *(float2*)(ob + (size_t)r0 * PD + nd * 8 + tc * 2) = w0;
            *(float2*)(ob + (size_t)r1 * PD + nd * 8 + tc * 2) = w1;
        }
    }
}

extern "C" void kernel_launch(void* const* d_in, const int* in_sizes, int n_in,
                              void* d_out, int out_size)
{
    const float* q    = (const float*)d_in[0];
    const float* k    = (const float*)d_in[1];
    const float* v    = (const float*)d_in[2];
    const float* pos  = (const float*)d_in[3];
    const float* mask = (const float*)d_in[4];
    float* out = (float*)d_out;

    static bool attr_set = false;
    if (!attr_set) {
        cudaFuncSetAttribute(attn_f16_w8_kernel,
                             cudaFuncAttributeMaxDynamicSharedMemorySize, SMEM_BYTES);
        attr_set = true;
    }

    prep_kv_kernel<<<dim3(PS / 32, PB * PH), 256>>>(k, v);
    dim3 grid((PS / TILE_M) * PB, PH);   // x: itile*8+b, y: h
    attn_f16_w8_kernel<<<grid, 256, SMEM_BYTES>>>(q, pos, mask, out);
}

// round 16
// speedup vs baseline: 1.1760x; 1.1760x over previous
#include <cuda_runtime.h>
#include <cuda_fp16.h>
#include <cstdint>

// Problem constants (B,H,S,D) = (8,8,2048,64)
#define PB 8
#define PH 8
#define PS 2048
#define PD 64
#define INV_T 0.125f
#define LOG2E 1.44269504f
#define EXP_OFF 5.77078016f   // 4 * log2(e): P = exp(sim - 4) = exp2(sim*log2e - OFF)

constexpr int TILE_M = 128;  // i-rows per CTA (4 warps x 32 rows)
constexpr int TILE_N = 32;   // j-cols per iteration
constexpr int QS  = 72;      // halves stride: sQ/sK rows (conflict-free frag reads)
constexpr int VSS = 40;      // halves stride: sVt rows (conflict-free frag reads)
constexpr int PMS = 40;      // words stride: pos/mkl rows (conflict-free float2 reads)

// ---- smem byte layout (identical to R11) ----
constexpr int KBUF_B   = TILE_N * QS * 2;         // 4608
constexpr int VBUF_B   = PD * VSS * 2;            // 5120
constexpr int REGA_B   = 2 * KBUF_B + 2 * VBUF_B; // 19456 (>= 18432 sQ prologue)
constexpr int PMPLANE_B = TILE_M * PMS * 4;       // 20480
constexpr int PM_B      = REGA_B;
constexpr int SMEM_BYTES = PM_B + 4 * PMPLANE_B;  // 101376 -> 2 CTAs/SM

// ---- persistent prepped operands ----
__device__ __half g_kh[(size_t)PB * PH * PS * PD];   // K fp16 row-major
__device__ __half g_vt[(size_t)PB * PH * PD * PS];   // V fp16 transposed (d-major)
__device__ float  g_ml[(size_t)PS * PS];             // mask * log2(e)

__device__ __forceinline__ uint32_t h2pack(float a, float b) {
    __half2 h = __floats2half2_rn(a, b);
    return *reinterpret_cast<uint32_t*>(&h);
}

__device__ __forceinline__ float ex2f(float x) {
    float r;
    asm("ex2.approx.ftz.f32 %0, %1;" : "=f"(r) : "f"(x));
    return r;
}

__device__ __forceinline__ void mma_f16(float c[4], const uint32_t a[4],
                                        uint32_t b0, uint32_t b1) {
    asm volatile(
        "mma.sync.aligned.m16n8k16.row.col.f32.f16.f16.f32 "
        "{%0,%1,%2,%3}, {%4,%5,%6,%7}, {%8,%9}, {%0,%1,%2,%3};"
        : "+f"(c[0]), "+f"(c[1]), "+f"(c[2]), "+f"(c[3])
        : "r"(a[0]), "r"(a[1]), "r"(a[2]), "r"(a[3]),
          "r"(b0), "r"(b1));
}

__device__ __forceinline__ uint32_t smem_u32(const void* p) {
    uint32_t a;
    asm("{ .reg .u64 t; cvta.to.shared.u64 t, %1; cvt.u32.u64 %0, t; }" : "=r"(a) : "l"(p));
    return a;
}

// ======= prep: K -> fp16, V -> fp16 transposed, mask -> mask*log2e =======
__global__ __launch_bounds__(256)
void prep_kv_kernel(const float* __restrict__ k, const float* __restrict__ v,
                    const float* __restrict__ mask)
{
    __shared__ __half sv[32][72];
    const int bh  = blockIdx.y;
    const int j0  = blockIdx.x * 32;
    const int tid = threadIdx.x;

    const float* kb = k + (size_t)bh * PS * PD;
    const float* vb = v + (size_t)bh * PS * PD;
    __half* khb = g_kh + (size_t)bh * PS * PD;
    __half* vtb = g_vt + (size_t)bh * PD * PS;

    #pragma unroll
    for (int p = 0; p < 2; ++p) {
        int idx = p * 256 + tid;
        int r = idx >> 4, c4 = idx & 15;
        float4 kf = *(const float4*)(kb + (size_t)(j0 + r) * PD + c4 * 4);
        *(uint2*)(khb + (size_t)(j0 + r) * PD + c4 * 4) =
            make_uint2(h2pack(kf.x, kf.y), h2pack(kf.z, kf.w));
        float4 vf = *(const float4*)(vb + (size_t)(j0 + r) * PD + c4 * 4);
        sv[r][c4 * 4 + 0] = __float2half_rn(vf.x);
        sv[r][c4 * 4 + 1] = __float2half_rn(vf.y);
        sv[r][c4 * 4 + 2] = __float2half_rn(vf.z);
        sv[r][c4 * 4 + 3] = __float2half_rn(vf.w);
    }

    // mask * log2e : 4096 blocks x 1024 floats each (one float4 per thread)
    {
        size_t mi = ((size_t)(blockIdx.y * gridDim.x + blockIdx.x) * 256 + tid) * 4;
        float4 m = *(const float4*)(mask + mi);
        *(float4*)(g_ml + mi) =
            make_float4(m.x * LOG2E, m.y * LOG2E, m.z * LOG2E, m.w * LOG2E);
    }
    __syncthreads();

    int d = tid >> 2, ch = tid & 3;
    __half hb[8];
    #pragma unroll
    for (int jj = 0; jj < 8; ++jj) hb[jj] = sv[ch * 8 + jj][d];
    *(uint4*)(vtb + (size_t)d * PS + j0 + ch * 8) = *(uint4*)hb;
}

// ================= main attention kernel (R11 structure) =================
__global__ __launch_bounds__(128, 2)
void attn_f16_ml_kernel(const float* __restrict__ q,
                        const float* __restrict__ pos,
                        float* __restrict__ out)
{
    extern __shared__ uint32_t smw[];
    char* smb = (char*)smw;
    const uint32_t sb = smem_u32(smw);

    const int bx   = blockIdx.x;                // itile*8 + b
    const int h    = blockIdx.y;
    const int b    = bx & 7;
    const int i0   = (bx >> 3) * TILE_M;
    const int tid  = threadIdx.x;
    const int warp = tid >> 5;
    const int lane = tid & 31;
    const int tg   = lane >> 2;
    const int tc   = lane & 3;

    const size_t bh = (size_t)(b * PH + h);
    const float*  qb   = q    + bh * (size_t)PS * PD;
    const __half* khb  = g_kh + bh * (size_t)PS * PD;
    const __half* vtb  = g_vt + bh * (size_t)PD * PS;
    const float*  posb = pos  + (size_t)h * PS * PS;
    float*        ob   = out  + bh * (size_t)PS * PD;

    // ---- stage K/Vt/pos/mkl for tile at j0t into buffer buf (all cp.async) ----
    auto issue_tile = [&](int j0t, int buf) {
        if (j0t < PS) {
            const __half* kg = khb + (size_t)j0t * PD;
            const __half* vg = vtb + j0t;
            uint32_t kbase = sb + buf * KBUF_B;
            uint32_t vbase = sb + 2 * KBUF_B + buf * VBUF_B;
            #pragma unroll
            for (int p = 0; p < 2; ++p) {
                int idx = p * 128 + tid;
                {   // K: 32 rows x 8 chunks of 16B
                    int r = idx >> 3, ch = idx & 7;
                    asm volatile("cp.async.cg.shared.global [%0], [%1], 16;"
                                 :: "r"(kbase + r * (QS * 2) + ch * 16),
                                    "l"(kg + (size_t)r * PD + ch * 8));
                }
                {   // Vt: 64 rows x 4 chunks of 16B
                    int r = idx >> 2, ch = idx & 3;
                    asm volatile("cp.async.cg.shared.global [%0], [%1], 16;"
                                 :: "r"(vbase + r * (VSS * 2) + ch * 16),
                                    "l"(vg + (size_t)r * PS + ch * 8));
                }
            }
            uint32_t pbase = sb + PM_B + buf * 2 * PMPLANE_B;
            uint32_t mbase = pbase + PMPLANE_B;
            #pragma unroll
            for (int p = 0; p < 8; ++p) {
                int idx = p * 128 + tid;          // 0..1023
                int r = idx >> 3, ch = idx & 7;   // row 0..127, 16B chunk 0..7
                asm volatile("cp.async.cg.shared.global [%0], [%1], 16;"
                             :: "r"(pbase + r * (PMS * 4) + ch * 16),
                                "l"(posb + (size_t)(i0 + r) * PS + j0t + ch * 4));
                asm volatile("cp.async.cg.shared.global [%0], [%1], 16;"
                             :: "r"(mbase + r * (PMS * 4) + ch * 16),
                                "l"(g_ml + (size_t)(i0 + r) * PS + j0t + ch * 4));
            }
        }
        asm volatile("cp.async.commit_group;" ::: "memory");
    };

    // ---- prologue: stage Q tile (128x64 fp16), cache fragments ----
    __half* sQh = (__half*)smb;
    #pragma unroll
    for (int p = 0; p < 16; ++p) {
        int idx = p * 128 + tid;
        int r = idx >> 4, c4 = idx & 15;
        float4 f = *(const float4*)(qb + (size_t)(i0 + r) * PD + c4 * 4);
        *(uint2*)&sQh[r * QS + c4 * 4] = make_uint2(h2pack(f.x, f.y), h2pack(f.z, f.w));
    }
    __syncthreads();

    uint32_t qa[2][4][4];
    #pragma unroll
    for (int blk = 0; blk < 2; ++blk) {
        const int rbase = warp * 32 + blk * 16;
        #pragma unroll
        for (int ks = 0; ks < 4; ++ks) {
            int c0 = ks * 16 + tc * 2;
            qa[blk][ks][0] = *(const uint32_t*)&sQh[(rbase + tg) * QS + c0];
            qa[blk][ks][1] = *(const uint32_t*)&sQh[(rbase + tg + 8) * QS + c0];
            qa[blk][ks][2] = *(const uint32_t*)&sQh[(rbase + tg) * QS + c0 + 8];
            qa[blk][ks][3] = *(const uint32_t*)&sQh[(rbase + tg + 8) * QS + c0 + 8];
        }
    }
    __syncthreads();           // region A becomes K/Vt buffers
    issue_tile(0, 0);          // G0

    float l_i[2][2] = {{0.f, 0.f}, {0.f, 0.f}};
    float o[2][8][4];
    #pragma unroll
    for (int blk = 0; blk < 2; ++blk)
        #pragma unroll
        for (int n = 0; n < 8; ++n)
            o[blk][n][0] = o[blk][n][1] = o[blk][n][2] = o[blk][n][3] = 0.f;

    for (int it = 0; it < PS / TILE_N; ++it) {
        const int buf = it & 1;
        __syncthreads();                             // WAR: prev readers of buf^1 done
        issue_tile((it + 1) * TILE_N, buf ^ 1);      // G(it+1)
        asm volatile("cp.async.wait_group 1;" ::: "memory");  // G(it) complete
        __syncthreads();                             // visibility

        const __half* sKh  = (const __half*)(smb + buf * KBUF_B);
        const __half* sVth = (const __half*)(smb + 2 * KBUF_B + buf * VBUF_B);
        const float* sPosB = (const float*)(smb + PM_B + buf * 2 * PMPLANE_B);
        const float* sMlB  = (const float*)(smb + PM_B + buf * 2 * PMPLANE_B + PMPLANE_B);

        // ---- S = Q K^T : both m16 blocks share each B fragment ----
        float c[2][4][4];
        #pragma unroll
        for (int blk = 0; blk < 2; ++blk)
            #pragma unroll
            for (int n = 0; n < 4; ++n)
                c[blk][n][0] = c[blk][n][1] = c[blk][n][2] = c[blk][n][3] = 0.f;
        #pragma unroll
        for (int ks = 0; ks < 4; ++ks) {
            #pragma unroll
            for (int n = 0; n < 4; ++n) {
                const __half* kr = &sKh[(n * 8 + tg) * QS + ks * 16 + tc * 2];
                uint32_t b0 = *(const uint32_t*)kr;
                uint32_t b1 = *(const uint32_t*)(kr + 8);
                mma_f16(c[0][n], qa[0][ks], b0, b1);
                mma_f16(c[1][n], qa[1][ks], b0, b1);
            }
        }

        // ---- P = exp2(mkl*(s*invT + pos) - OFF): 2 FMA + MUFU per element ----
        #pragma unroll
        for (int blk = 0; blk < 2; ++blk) {
            const int r0 = warp * 32 + blk * 16 + tg;
            const int r1 = r0 + 8;
            float rs0 = 0.f, rs1 = 0.f;
            #pragma unroll
            for (int n = 0; n < 4; ++n) {
                int col = n * 8 + tc * 2;
                float2 p0  = *(const float2*)&sPosB[r0 * PMS + col];
                float2 p1  = *(const float2*)&sPosB[r1 * PMS + col];
                float2 mk0 = *(const float2*)&sMlB[r0 * PMS + col];
                float2 mk1 = *(const float2*)&sMlB[r1 * PMS + col];
                c[blk][n][0] = ex2f(__fmaf_rn(__fmaf_rn(c[blk][n][0], INV_T, p0.x), mk0.x, -EXP_OFF));
                c[blk][n][1] = ex2f(__fmaf_rn(__fmaf_rn(c[blk][n][1], INV_T, p0.y), mk0.y, -EXP_OFF));
                c[blk][n][2] = ex2f(__fmaf_rn(__fmaf_rn(c[blk][n][2], INV_T, p1.x), mk1.x, -EXP_OFF));
                c[blk][n][3] = ex2f(__fmaf_rn(__fmaf_rn(c[blk][n][3], INV_T, p1.y), mk1.y, -EXP_OFF));
                rs0 += c[blk][n][0] + c[blk][n][1];
                rs1 += c[blk][n][2] + c[blk][n][3];
            }
            l_i[blk][0] += rs0;
            l_i[blk][1] += rs1;
        }

        // ---- O += P V : P A-frags from registers, V frags shared by blocks ----
        #pragma unroll
        for (int ks = 0; ks < 2; ++ks) {
            uint32_t pa[2][4];
            #pragma unroll
            for (int blk = 0; blk < 2; ++blk) {
                pa[blk][0] = h2pack(c[blk][2 * ks][0],     c[blk][2 * ks][1]);
                pa[blk][1] = h2pack(c[blk][2 * ks][2],     c[blk][2 * ks][3]);
                pa[blk][2] = h2pack(c[blk][2 * ks + 1][0], c[blk][2 * ks + 1][1]);
                pa[blk][3] = h2pack(c[blk][2 * ks + 1][2], c[blk][2 * ks + 1][3]);
            }
            #pragma unroll
            for (int nd = 0; nd < 8; ++nd) {
                const __half* vr = &sVth[(nd * 8 + tg) * VSS + ks * 16 + tc * 2];
                uint32_t b0 = *(const uint32_t*)vr;
                uint32_t b1 = *(const uint32_t*)(vr + 8);
                mma_f16(o[0][nd], pa[0], b0, b1);
                mma_f16(o[1][nd], pa[1], b0, b1);
            }
        }
    }

    // ---- epilogue: reduce l across group threads, normalize, write ----
    #pragma unroll
    for (int blk = 0; blk < 2; ++blk) {
        float l0 = l_i[blk][0], l1 = l_i[blk][1];
        l0 += __shfl_xor_sync(0xffffffffu, l0, 1);
        l0 += __shfl_xor_sync(0xffffffffu, l0, 2);
        l1 += __shfl_xor_sync(0xffffffffu, l1, 1);
        l1 += __shfl_xor_sync(0xffffffffu, l1, 2);
        const float inv0 = 1.f / l0;
        const float inv1 = 1.f / l1;
        const int r0 = i0 + warp * 32 + blk * 16 + tg;
        const int r1 = r0 + 8;
        #pragma unroll
        for (int nd = 0; nd < 8; ++nd) {
            float2 w0 = make_float2(o[blk][nd][0] * inv0, o[blk][nd][1] * inv0);
            float2 w1 = make_float2(o[blk][nd][2] * inv1, o[blk][nd][3] * inv1);
            *(float2*)(ob + (size_t)r0 * PD + nd * 8 + tc * 2) = w0;
            *(float2*)(ob + (size_t)r1 * PD + nd * 8 + tc * 2) = w1;
        }
    }
}

extern "C" void kernel_launch(void* const* d_in, const int* in_sizes, int n_in,
                              void* d_out, int out_size)
{
    const float* q    = (const float*)d_in[0];
    const float* k    = (const float*)d_in[1];
    const float* v    = (const float*)d_in[2];
    const float* pos  = (const float*)d_in[3];
    const float* mask = (const float*)d_in[4];
    float* out = (float*)d_out;

    static bool attr_set = false;
    if (!attr_set) {
        cudaFuncSetAttribute(attn_f16_ml_kernel,
                             cudaFuncAttributeMaxDynamicSharedMemorySize, SMEM_BYTES);
        attr_set = true;
    }

    prep_kv_kernel<<<dim3(PS / 32, PB * PH), 256>>>(k, v, mask);
    dim3 grid((PS / TILE_M) * PB, PH);   // x: itile*8+b (consecutive share itile & h), y: h
    attn_f16_ml_kernel<<<grid, 128, SMEM_BYTES>>>(q, pos, out);
}